// round 1
// baseline (speedup 1.0000x reference)
#include <cuda_runtime.h>
#include <cstdint>
#include <cstddef>

// ---------------------------------------------------------------------------
// PolicyHead: out = relu(x@W1^T+b1); q = out@W2^T+b2; k = out@W3^T+b3
// logits[b] = q_b @ k_b^T * SCALE (64x64x256 per block)
// promo from k rows 56..63 and w4; gather 1858 indices from full[4288].
// Round 1: tf32 mma.sync baseline, staged through __device__ scratch.
// ---------------------------------------------------------------------------

#define HDIM 256
#define MROWS_MAX 262144
#define PSCALE 0.0625f

// Scratch (allocation-free rule: __device__ globals)
__device__ float g_out[(size_t)MROWS_MAX * HDIM];
__device__ float g_q[(size_t)MROWS_MAX * HDIM];
__device__ float g_k[(size_t)MROWS_MAX * HDIM];

__device__ __forceinline__ unsigned f2tf(float f) {
    unsigned r;
    asm("cvt.rna.tf32.f32 %0, %1;" : "=r"(r) : "f"(f));
    return r;
}

// D += A(16x8) * B(8x8), tf32 inputs, fp32 accum
__device__ __forceinline__ void mma8(float* d, const unsigned* a, const unsigned* b) {
    asm volatile(
        "mma.sync.aligned.m16n8k8.row.col.f32.tf32.tf32.f32 "
        "{%0,%1,%2,%3}, {%4,%5,%6,%7}, {%8,%9}, {%0,%1,%2,%3};\n"
        : "+f"(d[0]), "+f"(d[1]), "+f"(d[2]), "+f"(d[3])
        : "r"(a[0]), "r"(a[1]), "r"(a[2]), "r"(a[3]), "r"(b[0]), "r"(b[1]));
}

// ---------------------------------------------------------------------------
// GEMM: C[M,256] = act(A[M,256] @ W[256,256]^T + bias)
// Tile 128x128, BK=32, 8 warps (warp tile 32x64), tf32 mma.
// smem stride 36 words: fragment bank = (row*36 + t) % 32 = row*4 + t  (no conflicts)
// ---------------------------------------------------------------------------
template <bool RELU>
__global__ __launch_bounds__(256, 2)
void gemm_kernel(const float* __restrict__ A, const float* __restrict__ W,
                 const float* __restrict__ bias, float* __restrict__ C) {
    __shared__ unsigned As[128 * 36];
    __shared__ unsigned Bs[128 * 36];
    const int m0 = blockIdx.y * 128;
    const int n0 = blockIdx.x * 128;
    const int tid = threadIdx.x;
    const int warp = tid >> 5, lane = tid & 31;
    const int g = lane >> 2, t = lane & 3;
    const int wm = warp >> 1, wn = warp & 1;   // warp tile origin (wm*32, wn*64)

    float acc[2][8][4];
#pragma unroll
    for (int i = 0; i < 2; i++)
#pragma unroll
        for (int j = 0; j < 8; j++)
#pragma unroll
            for (int l = 0; l < 4; l++) acc[i][j][l] = 0.f;

    const int lrow = tid >> 3;        // 0..31
    const int lcol = (tid & 7) * 4;   // 0..28

    for (int k0 = 0; k0 < HDIM; k0 += 32) {
#pragma unroll
        for (int i = 0; i < 4; i++) {
            int row = lrow + i * 32;
            float4 va = *(const float4*)(A + (size_t)(m0 + row) * HDIM + k0 + lcol);
            unsigned* d = &As[row * 36 + lcol];
            d[0] = f2tf(va.x); d[1] = f2tf(va.y); d[2] = f2tf(va.z); d[3] = f2tf(va.w);
            float4 vb = *(const float4*)(W + (size_t)(n0 + row) * HDIM + k0 + lcol);
            unsigned* e = &Bs[row * 36 + lcol];
            e[0] = f2tf(vb.x); e[1] = f2tf(vb.y); e[2] = f2tf(vb.z); e[3] = f2tf(vb.w);
        }
        __syncthreads();
#pragma unroll
        for (int ks = 0; ks < 32; ks += 8) {
            unsigned a[2][4], b[8][2];
#pragma unroll
            for (int mi = 0; mi < 2; mi++) {
                int r = wm * 32 + mi * 16;
                a[mi][0] = As[(r + g) * 36 + ks + t];
                a[mi][1] = As[(r + g + 8) * 36 + ks + t];
                a[mi][2] = As[(r + g) * 36 + ks + t + 4];
                a[mi][3] = As[(r + g + 8) * 36 + ks + t + 4];
            }
#pragma unroll
            for (int ni = 0; ni < 8; ni++) {
                int c = wn * 64 + ni * 8;
                b[ni][0] = Bs[(c + g) * 36 + ks + t];
                b[ni][1] = Bs[(c + g) * 36 + ks + t + 4];
            }
#pragma unroll
            for (int mi = 0; mi < 2; mi++)
#pragma unroll
                for (int ni = 0; ni < 8; ni++)
                    mma8(acc[mi][ni], a[mi], b[ni]);
        }
        __syncthreads();
    }
    // epilogue: bias (+relu), float2 stores
#pragma unroll
    for (int mi = 0; mi < 2; mi++) {
#pragma unroll
        for (int h = 0; h < 2; h++) {
            int r = m0 + wm * 32 + mi * 16 + g + h * 8;
#pragma unroll
            for (int ni = 0; ni < 8; ni++) {
                int c = n0 + wn * 64 + ni * 8 + 2 * t;
                float v0 = acc[mi][ni][h * 2 + 0] + bias[c];
                float v1 = acc[mi][ni][h * 2 + 1] + bias[c + 1];
                if (RELU) { v0 = fmaxf(v0, 0.f); v1 = fmaxf(v1, 0.f); }
                *(float2*)(C + (size_t)r * HDIM + c) = make_float2(v0, v1);
            }
        }
    }
}

// ---------------------------------------------------------------------------
// Attention + promo + gather. One CTA per 64-row block.
// qs/ks hold tf32 bit patterns (valid fp32 values, low mantissa zeroed) with
// stride 260 words for conflict-free mma fragment loads.
// ---------------------------------------------------------------------------
constexpr int QSTRIDE = 260;

__global__ __launch_bounds__(256, 1)
void att_kernel(const float* __restrict__ Q, const float* __restrict__ Kf,
                const float* __restrict__ w4, const int* __restrict__ gidx,
                float* __restrict__ out) {
    extern __shared__ unsigned sm[];
    unsigned* qs = sm;                            // 64 * 260
    unsigned* ks = sm + 64 * QSTRIDE;             // 64 * 260
    float* fulls = (float*)(sm + 2 * 64 * QSTRIDE);  // 4288 (+pad)
    float* offs_sm = fulls + 4288;                // 32

    const int b = blockIdx.x;
    const int tid = threadIdx.x;
    const float* qg = Q + (size_t)b * 64 * HDIM;
    const float* kg = Kf + (size_t)b * 64 * HDIM;

    for (int i = tid * 4; i < 64 * HDIM; i += 256 * 4) {
        int row = i >> 8, col = i & 255;
        float4 v = *(const float4*)(qg + i);
        unsigned* d = &qs[row * QSTRIDE + col];
        d[0] = f2tf(v.x); d[1] = f2tf(v.y); d[2] = f2tf(v.z); d[3] = f2tf(v.w);
        float4 w = *(const float4*)(kg + i);
        unsigned* e = &ks[row * QSTRIDE + col];
        e[0] = f2tf(w.x); e[1] = f2tf(w.y); e[2] = f2tf(w.z); e[3] = f2tf(w.w);
    }
    __syncthreads();

    const int warp = tid >> 5, lane = tid & 31;
    const int g = lane >> 2, t = lane & 3;
    const int wm = warp >> 1, wn = warp & 1;   // warp tile 16x32; grid 4(m) x 2(n)

    float acc[4][4];
#pragma unroll
    for (int i = 0; i < 4; i++)
#pragma unroll
        for (int j = 0; j < 4; j++) acc[i][j] = 0.f;

    for (int k8 = 0; k8 < HDIM; k8 += 8) {
        unsigned a[4], bb[4][2];
        int r = wm * 16;
        a[0] = qs[(r + g) * QSTRIDE + k8 + t];
        a[1] = qs[(r + g + 8) * QSTRIDE + k8 + t];
        a[2] = qs[(r + g) * QSTRIDE + k8 + t + 4];
        a[3] = qs[(r + g + 8) * QSTRIDE + k8 + t + 4];
#pragma unroll
        for (int ni = 0; ni < 4; ni++) {
            int c = wn * 32 + ni * 8;
            bb[ni][0] = ks[(c + g) * QSTRIDE + k8 + t];
            bb[ni][1] = ks[(c + g) * QSTRIDE + k8 + t + 4];
        }
#pragma unroll
        for (int ni = 0; ni < 4; ni++) mma8(acc[ni], a, bb[ni]);
    }
    // scaled logits -> fulls[0..4095]
#pragma unroll
    for (int ni = 0; ni < 4; ni++) {
        int c = wn * 32 + ni * 8 + 2 * t;
        int r0 = wm * 16 + g;
        fulls[r0 * 64 + c]           = acc[ni][0] * PSCALE;
        fulls[r0 * 64 + c + 1]       = acc[ni][1] * PSCALE;
        fulls[(r0 + 8) * 64 + c]     = acc[ni][2] * PSCALE;
        fulls[(r0 + 8) * 64 + c + 1] = acc[ni][3] * PSCALE;
    }
    __syncthreads();

    // offs[p][s] = dot(k[56+s], w4[p]) — one lane per (p,s)
    if (warp == 0) {
        int p = lane >> 3, s = lane & 7;
        const float* w4r = w4 + p * HDIM;
        const unsigned* kr = &ks[(56 + s) * QSTRIDE];
        float sum = 0.f;
#pragma unroll 8
        for (int hh = 0; hh < HDIM; hh++)
            sum += __uint_as_float(kr[hh]) * w4r[hh];
        offs_sm[lane] = sum;   // [p*8 + s]
    }
    __syncthreads();

    // promo: fulls[4096 + qq*24 + s*3 + p] = offs[p][s] + offs[3][s] + logits[48+qq][56+s]
    if (tid < 192) {
        int qq = tid / 24, rr = tid % 24, s = rr / 3, p = rr % 3;
        fulls[4096 + tid] = offs_sm[p * 8 + s] + offs_sm[24 + s]
                          + fulls[(48 + qq) * 64 + 56 + s];
    }
    __syncthreads();

    // gather -> coalesced output
    float* ob = out + (size_t)b * 1858;
    for (int i = tid; i < 1858; i += 256) ob[i] = fulls[gidx[i]];
}

// ---------------------------------------------------------------------------
extern "C" void kernel_launch(void* const* d_in, const int* in_sizes, int n_in,
                              void* d_out, int out_size) {
    const float* x  = (const float*)d_in[0];
    const float* w1 = (const float*)d_in[1];
    const float* b1 = (const float*)d_in[2];
    const float* w2 = (const float*)d_in[3];
    const float* b2 = (const float*)d_in[4];
    const float* w3 = (const float*)d_in[5];
    const float* b3 = (const float*)d_in[6];
    const float* w4 = (const float*)d_in[7];
    const int*   gi = (const int*)d_in[8];
    float* out = (float*)d_out;

    const int M = in_sizes[0] / HDIM;     // 262144
    const int nblk = M / 64;              // 4096

    float *o, *q, *k;
    cudaGetSymbolAddress((void**)&o, g_out);
    cudaGetSymbolAddress((void**)&q, g_q);
    cudaGetSymbolAddress((void**)&k, g_k);

    dim3 gg(HDIM / 128, M / 128);
    gemm_kernel<true><<<gg, 256>>>(x, w1, b1, o);
    gemm_kernel<false><<<gg, 256>>>(o, w2, b2, q);
    gemm_kernel<false><<<gg, 256>>>(o, w3, b3, k);

    size_t shmem = (size_t)(2 * 64 * QSTRIDE + 4288 + 64) * sizeof(unsigned);
    cudaFuncSetAttribute((const void*)att_kernel,
                         cudaFuncAttributeMaxDynamicSharedMemorySize, (int)shmem);
    att_kernel<<<nblk, 256, shmem>>>(q, k, w4, gi, out);
}